// round 14
// baseline (speedup 1.0000x reference)
#include <cuda_runtime.h>
#include <cuda_fp16.h>
#include <math.h>
#include <stdint.h>

// ---------------------------------------------------------------------------
// Problem constants
// ---------------------------------------------------------------------------
#define EMBED  768
#define NWIN   200
#define NTOK   196
#define NHEAD  12
#define HD     64
#define M_TOK  32768
#define FFDIM  3072
#define QKVN   2304

// ---------------------------------------------------------------------------
// Scratch (device globals; no allocation allowed)
// ---------------------------------------------------------------------------
__device__ __half g_hwin[(size_t)M_TOK*EMBED];
__device__ __half g_qkv [(size_t)M_TOK*QKVN];
__device__ __half g_attn[(size_t)M_TOK*EMBED];
__device__ float  g_x1  [(size_t)M_TOK*EMBED];
__device__ __half g_h2  [(size_t)M_TOK*EMBED];
__device__ __half g_ff  [(size_t)M_TOK*FFDIM];
__device__ __half g_bq16[QKVN];
// transposed fp16 weights: [N][K]
__device__ __half g_wqkv[(size_t)QKVN*EMBED];
__device__ __half g_wprj[(size_t)EMBED*EMBED];
__device__ __half g_wfc1[(size_t)FFDIM*EMBED];
__device__ __half g_wfc2[(size_t)EMBED*FFDIM];

// ---------------------------------------------------------------------------
// Helpers
// ---------------------------------------------------------------------------
__device__ __forceinline__ float gelu_f(float v) {
    return 0.5f * v * (1.0f + erff(v * 0.7071067811865476f));
}
__device__ __forceinline__ uint32_t s2u(const void* p) {
    uint32_t a;
    asm("{ .reg .u64 t; cvta.to.shared.u64 t, %1; cvt.u32.u64 %0, t; }" : "=r"(a) : "l"(p));
    return a;
}
__device__ __forceinline__ void ldsm_x4(uint32_t& r0, uint32_t& r1, uint32_t& r2,
                                        uint32_t& r3, uint32_t addr) {
    asm volatile("ldmatrix.sync.aligned.m8n8.x4.shared.b16 {%0,%1,%2,%3}, [%4];"
                 : "=r"(r0), "=r"(r1), "=r"(r2), "=r"(r3) : "r"(addr));
}
__device__ __forceinline__ void ldsm_x4t(uint32_t& r0, uint32_t& r1, uint32_t& r2,
                                         uint32_t& r3, uint32_t addr) {
    asm volatile("ldmatrix.sync.aligned.m8n8.x4.trans.shared.b16 {%0,%1,%2,%3}, [%4];"
                 : "=r"(r0), "=r"(r1), "=r"(r2), "=r"(r3) : "r"(addr));
}
__device__ __forceinline__ void mma16816(float* c, const uint32_t* a,
                                         uint32_t b0, uint32_t b1) {
    asm volatile(
        "mma.sync.aligned.m16n8k16.row.col.f32.f16.f16.f32 "
        "{%0,%1,%2,%3}, {%4,%5,%6,%7}, {%8,%9}, {%0,%1,%2,%3};"
        : "+f"(c[0]), "+f"(c[1]), "+f"(c[2]), "+f"(c[3])
        : "r"(a[0]), "r"(a[1]), "r"(a[2]), "r"(a[3]), "r"(b0), "r"(b1));
}
__device__ __forceinline__ void cp16(uint32_t saddr, const void* g) {
    asm volatile("cp.async.cg.shared.global [%0], [%1], 16;" :: "r"(saddr), "l"(g));
}
__device__ __forceinline__ void cp_commit() {
    asm volatile("cp.async.commit_group;");
}
__device__ __forceinline__ uint32_t packh2(float a, float b) {
    __half2 h = __floats2half2_rn(a, b);
    return *reinterpret_cast<uint32_t*>(&h);
}

// ---------------------------------------------------------------------------
// Weight prep: transpose [K,N] fp32 -> [N,K] fp16
// ---------------------------------------------------------------------------
__global__ __launch_bounds__(256) void wprep(
    const float* __restrict__ W, __half* __restrict__ T, int K, int N)
{
    __shared__ float t[32][33];
    const int n0 = blockIdx.x * 32, k0 = blockIdx.y * 32;
    const int tx = threadIdx.x & 31, ty = threadIdx.x >> 5;
    #pragma unroll
    for (int i = 0; i < 32; i += 8)
        t[ty + i][tx] = W[(size_t)(k0 + ty + i) * N + n0 + tx];
    __syncthreads();
    #pragma unroll
    for (int i = 0; i < 32; i += 8)
        T[(size_t)(n0 + ty + i) * K + k0 + tx] = __float2half(t[tx][ty + i]);
}

__global__ void bprep(const float* __restrict__ b, __half* __restrict__ o, int n) {
    int i = blockIdx.x * 256 + threadIdx.x;
    if (i < n) o[i] = __float2half(b[i]);
}

// ---------------------------------------------------------------------------
// LayerNorm -> fp16
// ---------------------------------------------------------------------------
__global__ __launch_bounds__(256) void ln_kernel(
    const float* __restrict__ xin, const float* __restrict__ g,
    const float* __restrict__ b, __half* __restrict__ oh)
{
    __shared__ float red[16];
    const int row = blockIdx.x, tid = threadIdx.x;
    const float* xr = xin + (size_t)row * EMBED;
    const size_t ro = (size_t)row * EMBED;
    float v0 = xr[tid], v1 = xr[tid+256], v2 = xr[tid+512];
    float s = v0+v1+v2, s2 = v0*v0+v1*v1+v2*v2;
    #pragma unroll
    for (int o = 16; o; o >>= 1) {
        s  += __shfl_xor_sync(0xffffffffu, s,  o);
        s2 += __shfl_xor_sync(0xffffffffu, s2, o);
    }
    if ((tid & 31) == 0) { red[tid>>5] = s; red[8+(tid>>5)] = s2; }
    __syncthreads();
    float S=0.f, S2=0.f;
    #pragma unroll
    for (int i = 0; i < 8; i++) { S += red[i]; S2 += red[8+i]; }
    const float mean = S * (1.f/768.f);
    const float rstd = rsqrtf(S2*(1.f/768.f) - mean*mean + 1e-6f);
    oh[ro+tid]     = __float2half((v0-mean)*rstd*g[tid]     + b[tid]);
    oh[ro+tid+256] = __float2half((v1-mean)*rstd*g[tid+256] + b[tid+256]);
    oh[ro+tid+512] = __float2half((v2-mean)*rstd*g[tid+512] + b[tid+512]);
}

// ---------------------------------------------------------------------------
// HMMA GEMM (fp16): C[M,N] = A[M,K] @ B[N,K]^T (+bias).
// CTA 256x128, 8 warps as 4(M)x2(N), each 64x64. K-chunk 64, double-buffered.
// M % 256 == 0, N % 128 == 0, K % 64 == 0.
// EPI: 0 bias->fp32 | 1 bias+gelu->fp16 | 2 bias+res->fp32 | 3 bias->fp16
// ---------------------------------------------------------------------------
#define LDA        72                       // halves per smem row (64 + 8 pad)
#define A_TILE_B   (256*LDA*2)              // 36864
#define B_TILE_B   (128*LDA*2)              // 18432
#define STAGE_B    (A_TILE_B + B_TILE_B)    // 55296
#define GSM_BYTES  (2*STAGE_B)              // 110592

template<int EPI>
__global__ __launch_bounds__(256, 1) void tgemm(
    const __half* __restrict__ A, const __half* __restrict__ B,
    const float* __restrict__ bias, float* __restrict__ Co,
    __half* __restrict__ Ch, int M, int N, int K, const float* __restrict__ res)
{
    extern __shared__ char smc[];
    const uint32_t smb = s2u(smc);
    const int tid = threadIdx.x;
    const int wid = tid >> 5, lane = tid & 31;
    const int bm = blockIdx.y * 256, bn = blockIdx.x * 128;
    const int wm = wid & 3, wn = wid >> 2;   // warp tile: 64(M) x 64(N)
    const int NC = K >> 6;                    // K-chunks of 64

    float acc[4][8][4];
    #pragma unroll
    for (int i = 0; i < 4; i++)
        #pragma unroll
        for (int j = 0; j < 8; j++)
            #pragma unroll
            for (int k = 0; k < 4; k++) acc[i][j][k] = 0.f;

    const uint32_t offA = (uint32_t)((wm*64 + (lane & 7) + 8*((lane >> 3) & 1)) * LDA
                                     + 8*(lane >> 4)) * 2;
    const uint32_t offB = (uint32_t)((wn*64 + (lane & 7) + 8*(lane >> 4)) * LDA
                                     + 8*((lane >> 3) & 1)) * 2;

    auto load_chunk = [&](int c, int b) {
        const int k0 = c << 6;
        const uint32_t bb = smb + b * STAGE_B;
        #pragma unroll
        for (int s = 0; s < 8; s++) {               // A: 256 rows x 8 segs
            const int u = tid + s * 256;            // [0,2048)
            const int row = u >> 3, seg = u & 7;
            cp16(bb + (uint32_t)(row * LDA + seg * 8) * 2,
                 A + (size_t)(bm + row) * K + k0 + seg * 8);
        }
        #pragma unroll
        for (int s = 0; s < 4; s++) {               // B: 128 rows x 8 segs
            const int u = tid + s * 256;            // [0,1024)
            const int row = u >> 3, seg = u & 7;
            cp16(bb + A_TILE_B + (uint32_t)(row * LDA + seg * 8) * 2,
                 B + (size_t)(bn + row) * K + k0 + seg * 8);
        }
        cp_commit();
    };

    load_chunk(0, 0);

    for (int c = 0; c < NC; c++) {
        const int b = c & 1;
        if (c + 1 < NC) {
            load_chunk(c + 1, b ^ 1);
            asm volatile("cp.async.wait_group 1;");
        } else {
            asm volatile("cp.async.wait_group 0;");
        }
        __syncthreads();

        const uint32_t bb = smb + b * STAGE_B;
        const uint32_t pA = bb + offA;
        const uint32_t pB = bb + A_TILE_B + offB;

        #pragma unroll
        for (int ks = 0; ks < 4; ks++) {
            const uint32_t kso = ks * 32;            // 16 halves = 32 bytes
            uint32_t ah[4][4], bh[8][2];
            #pragma unroll
            for (int mt = 0; mt < 4; mt++)
                ldsm_x4(ah[mt][0], ah[mt][1], ah[mt][2], ah[mt][3],
                        pA + kso + mt * (16*LDA*2));
            #pragma unroll
            for (int L = 0; L < 4; L++)
                ldsm_x4(bh[2*L][0], bh[2*L][1], bh[2*L+1][0], bh[2*L+1][1],
                        pB + kso + L * (16*LDA*2));
            #pragma unroll
            for (int mt = 0; mt < 4; mt++)
                #pragma unroll
                for (int nt = 0; nt < 8; nt++)
                    mma16816(acc[mt][nt], ah[mt], bh[nt][0], bh[nt][1]);
        }
        __syncthreads();
    }

    const int rbase = bm + wm*64;
    const int nbase = bn + wn*64;
    #pragma unroll
    for (int mt = 0; mt < 4; mt++) {
        #pragma unroll
        for (int half = 0; half < 2; half++) {
            const int m = rbase + mt*16 + (lane >> 2) + half*8;
            #pragma unroll
            for (int nt = 0; nt < 8; nt++) {
                const int n = nbase + nt*8 + (lane & 3)*2;
                float v0 = acc[mt][nt][half*2 + 0] + bias[n];
                float v1 = acc[mt][nt][half*2 + 1] + bias[n + 1];
                if (EPI == 0) {
                    *(float2*)(Co + (size_t)m * N + n) = make_float2(v0, v1);
                } else if (EPI == 1) {
                    __half2 H;
                    H.x = __float2half(gelu_f(v0));
                    H.y = __float2half(gelu_f(v1));
                    *(__half2*)(Ch + (size_t)m * N + n) = H;
                } else if (EPI == 2) {
                    const float2 r2 = *(const float2*)(res + (size_t)m * N + n);
                    *(float2*)(Co + (size_t)m * N + n) = make_float2(v0 + r2.x, v1 + r2.y);
                } else {
                    __half2 H;
                    H.x = __float2half(v0); H.y = __float2half(v1);
                    *(__half2*)(Ch + (size_t)m * N + n) = H;
                }
            }
        }
    }
}

// ---------------------------------------------------------------------------
// FA2-style window attention on mma.sync. One (window, head) per CTA.
// ---------------------------------------------------------------------------
#define LDH   72           // halves per smem row
#define LDR   72           // rel-pos table row stride (bank-spread)
#define NPAD  208          // tokens padded to 13 x m16
#define OFF_Q 0
#define OFF_K (NPAD*LDH*2)
#define OFF_V (2*NPAD*LDH*2)
#define OFF_RH (3*NPAD*LDH*2)          // 27*LDR halves
#define OFF_RW (OFF_RH + 27*LDR*2)
#define OFF_BH (OFF_RW + 27*LDR*2)     // 196*14 halves
#define OFF_BW (OFF_BH + 196*14*2)
#define ATTN_SMEM (OFF_BW + 196*14*2)  // 108608 B

__global__ __launch_bounds__(256, 2) void attn_kernel(
    const __half* __restrict__ qkv, const __half* __restrict__ bq16,
    const float* __restrict__ relh, const float* __restrict__ relw,
    __half* __restrict__ ao)
{
    extern __shared__ char smc[];
    const uint32_t smb = s2u(smc);
    __half* Qh = (__half*)(smc + OFF_Q);
    __half* Kh = (__half*)(smc + OFF_K);
    __half* Vh = (__half*)(smc + OFF_V);
    __half* Rh = (__half*)(smc + OFF_RH);
    __half* Rw = (__half*)(smc + OFF_RW);
    __half* BH = (__half*)(smc + OFF_BH);
    __half* BW = (__half*)(smc + OFF_BW);

    const int tid = threadIdx.x;
    const int w = blockIdx.x / NHEAD, h = blockIdx.x % NHEAD;
    const int bI = w / 25, wr = w % 25;
    const int wy = wr / 5, wx = wr % 5;
    const int wid = tid >> 5, lane = tid & 31;

    // ---- load Q,K,V (fp16) with window gather; pad rows with zeros ----
    for (int idx = tid; idx < NTOK * 8; idx += 256) {
        const int t = idx >> 3, seg = idx & 7;
        const int y = wy * 14 + t / 14, xx = wx * 14 + t % 14;
        const __half* rp = (y < 64 && xx < 64)
            ? qkv + (size_t)((bI * 64 + y) * 64 + xx) * QKVN + h * HD + seg * 8
            : bq16 + h * HD + seg * 8;
        *(uint4*)&Qh[t * LDH + seg * 8] = *(const uint4*)(rp);
        *(uint4*)&Kh[t * LDH + seg * 8] = *(const uint4*)(rp + 768);
        *(uint4*)&Vh[t * LDH + seg * 8] = *(const uint4*)(rp + 1536);
    }
    for (int idx = tid; idx < (NPAD - NTOK) * 8; idx += 256) {
        const int t = NTOK + (idx >> 3), seg = idx & 7;
        const uint4 z = make_uint4(0, 0, 0, 0);
        *(uint4*)&Qh[t * LDH + seg * 8] = z;
        *(uint4*)&Kh[t * LDH + seg * 8] = z;
        *(uint4*)&Vh[t * LDH + seg * 8] = z;
    }
    for (int idx = tid; idx < 27 * 64; idx += 256) {
        const int rr = idx >> 6, cc = idx & 63;
        Rh[rr * LDR + cc] = __float2half(relh[idx]);
        Rw[rr * LDR + cc] = __float2half(relw[idx]);
    }
    __syncthreads();

    // ---- rel-pos bias tables: lane L owns (r = L>>1, d-half = L&1) ----
    for (int i = wid; i < NTOK; i += 8) {
        const int p = i / 14, qc = i % 14;
        if (lane < 28) {
            const int r = lane >> 1, hf = lane & 1;
            const __half* qrow  = &Qh[i * LDH + hf * 32];
            const __half* rhrow = &Rh[(p  + 13 - r) * LDR + hf * 32];
            const __half* rwrow = &Rw[(qc + 13 - r) * LDR + hf * 32];
            float ah = 0.f, aw = 0.f;
            #pragma unroll
            for (int k = 0; k < 16; k++) {
                const float2 q2 = __half22float2(*(const __half2*)(qrow + 2*k));
                const float2 h2 = __half22float2(*(const __half2*)(rhrow + 2*k));
                const float2 w2 = __half22float2(*(const __half2*)(rwrow + 2*k));
                ah += q2.x * h2.x + q2.y * h2.y;
                aw += q2.x * w2.x + q2.y * w2.y;
            }
            ah += __shfl_xor_sync(0x0fffffffu, ah, 1);
            aw += __shfl_xor_sync(0x0fffffffu, aw, 1);
            if (hf == 0) {
                BH[i*14 + r] = __float2half(ah);
                BW[i*14 + r] = __float2half(aw);
            }
        }
    }
    __syncthreads();

    const float SCALE = 0.125f;
    const uint32_t qb = smb + OFF_Q, kb = smb + OFF_K, vb = smb + OFF_V;

    // ---- per m16 tile: online-softmax FA loop over 13 key chunks of 16 ----
    for (int tile = wid; tile < 13; tile += 8) {
        uint32_t aq[4][4];
        #pragma unroll
        for (int kk = 0; kk < 4; kk++)
            ldsm_x4(aq[kk][0], aq[kk][1], aq[kk][2], aq[kk][3],
                    qb + (uint32_t)((tile*16 + (lane&7) + 8*((lane>>3)&1)) * LDH
                                    + kk*16 + 8*(lane>>4)) * 2);

        float o[8][4];
        #pragma unroll
        for (int i = 0; i < 8; i++)
            #pragma unroll
            for (int j = 0; j < 4; j++) o[i][j] = 0.f;
        float mrun0 = -1e30f, mrun1 = -1e30f, lrun0 = 0.f, lrun1 = 0.f;

        const int i0 = tile*16 + (lane >> 2);
        const int i0c = (i0 < NTOK ? i0 : 0), i1c = (i0 + 8 < NTOK ? i0 + 8 : 0);

        for (int kc = 0; kc < 13; kc++) {
            float S0[4], S1[4];
            #pragma unroll
            for (int j = 0; j < 4; j++) { S0[j] = 0.f; S1[j] = 0.f; }
            #pragma unroll
            for (int kk = 0; kk < 4; kk++) {
                uint32_t r0, r1, r2, r3;
                ldsm_x4(r0, r1, r2, r3,
                        kb + (uint32_t)((kc*16 + (lane&7) + 8*(lane>>4)) * LDH
                                        + kk*16 + 8*((lane>>3)&1)) * 2);
                mma16816(S0, aq[kk], r0, r1);
                mma16816(S1, aq[kk], r2, r3);
            }
            const int j0 = kc*16 + 2*(lane & 3);
            float s[2][4];
            #pragma unroll
            for (int e = 0; e < 4; e++) {
                const int j = j0 + (e & 1) + (e >> 1) * 8;
                bool ok = (j < NTOK);
                int jp = 0, jq = 0;
                if (ok) { jp = j / 14; jq = j - jp * 14; }
                const float b0 = __half2float(BH[i0c*14+jp]) + __half2float(BW[i0c*14+jq]);
                const float b1 = __half2float(BH[i1c*14+jp]) + __half2float(BW[i1c*14+jq]);
                const float r0v = (e >> 1) ? S1[e & 1] : S0[e & 1];
                const float r1v = (e >> 1) ? S1[2 + (e & 1)] : S0[2 + (e & 1)];
                s[0][e] = ok ? r0v * SCALE + b0 : -1e30f;
                s[1][e] = ok ? r1v * SCALE + b1 : -1e30f;
            }
            float mx0 = fmaxf(fmaxf(s[0][0], s[0][1]), fmaxf(s[0][2], s[0][3]));
            float mx1 = fmaxf(fmaxf(s[1][0], s[1][1]), fmaxf(s[1][2], s[1][3]));
            mx0 = fmaxf(mx0, __shfl_xor_sync(0xffffffffu, mx0, 1));
            mx0 = fmaxf(mx0, __shfl_xor_sync(0xffffffffu, mx0, 2));
            mx1 = fmaxf(mx1, __shfl_xor_sync(0xffffffffu, mx1, 1));
            mx1 = fmaxf(mx1, __shfl_xor_sync(0xffffffffu, mx1, 2));
            const float mn0 = fmaxf(mrun0, mx0), mn1 = fmaxf(mrun1, mx1);
            float sc0 = 1.f, sc1 = 1.f;
            const bool nochange = (mn0 == mrun0) && (mn1 == mrun1);
            if (!__all_sync(0xffffffffu, nochange)) {
                sc0 = __expf(mrun0 - mn0);
                sc1 = __expf(mrun1 - mn1);
                #pragma unroll
                for (int dt = 0; dt < 8; dt++) {
                    o[dt][0] *= sc0; o[dt][1] *= sc0;
                    o[dt][2] *= sc1; o[dt][3] *= sc1;
                }
            }
            mrun0 = mn0; mrun1 = mn1;
            float p[2][4], rs0 = 0.f, rs1 = 0.f;
            #pragma unroll
            for (int e = 0; e < 4; e++) {
                p[0][e] = __expf(s[0][e] - mn0);
                p[1][e] = __expf(s[1][e] - mn1);
                rs0 += p[0][e]; rs1 += p[1][e];
            }
            rs0 += __shfl_xor_sync(0xffffffffu, rs0, 1);
            rs0 += __shfl_xor_sync(0xffffffffu, rs0, 2);
            rs1 += __shfl_xor_sync(0xffffffffu, rs1, 1);
            rs1 += __shfl_xor_sync(0xffffffffu, rs1, 2);
            lrun0 = lrun0 * sc0 + rs0;
            lrun1 = lrun1 * sc1 + rs1;
            uint32_t ap[4];
            ap[0] = packh2(p[0][0], p[0][1]);
            ap[1] = packh2(p[1][0], p[1][1]);
            ap[2] = packh2(p[0][2], p[0][3]);
            ap[3] = packh2(p[1][2], p[1][3]);
            #pragma unroll
            for (int nn = 0; nn < 4; nn++) {
                uint32_t r0, r1, r2, r3;
                ldsm_x4t(r0, r1, r2, r3,
                         vb + (uint32_t)((kc*16 + (lane & 15)) * LDH
                                         + nn*16 + 8*(lane>>4)) * 2);
                mma16816(o[2*nn],     ap, r0, r1);
                mma16816(o[2*nn + 1], ap, r2, r3);
            }
        }

        // ---- write out (scatter to compact layout) ----
        const float inv0 = 1.f / lrun0, inv1 = 1.f / lrun1;
        #pragma unroll
        for (int half = 0; half < 2; half++) {
            const int i = tile*16 + (lane >> 2) + half*8;
            if (i >= NTOK) continue;
            const int y = wy*14 + i/14, xx = wx*14 + i%14;
            if (y >= 64 || xx >= 64) continue;
            __half* orow = ao + (size_t)((bI*64 + y)*64 + xx) * EMBED + h * HD;
            const float inv = half ? inv1 : inv0;
            #pragma unroll
            for (int dt = 0; dt < 8; dt++) {
                __half2 H;
                H.x = __float2half(o[dt][half*2 + 0] * inv);
                H.y = __float2half(o[dt][half*2 + 1] * inv);
                *(__half2*)(orow + dt*8 + 2*(lane & 3)) = H;
            }
        }
    }
}

// ---------------------------------------------------------------------------
// kernel_launch
// ---------------------------------------------------------------------------
extern "C" void kernel_launch(void* const* d_in, const int* in_sizes, int n_in,
                              void* d_out, int out_size)
{
    const float* x      = (const float*)d_in[0];
    const float* g1     = (const float*)d_in[1];
    const float* beta1  = (const float*)d_in[2];
    const float* w_qkv  = (const float*)d_in[3];
    const float* b_qkv  = (const float*)d_in[4];
    const float* w_proj = (const float*)d_in[5];
    const float* b_proj = (const float*)d_in[6];
    const float* relh   = (const float*)d_in[7];
    const float* relw   = (const float*)d_in[8];
    const float* g2     = (const float*)d_in[9];
    const float* beta2  = (const float*)d_in[10];
    const float* w_fc1  = (const float*)d_in[11];
    const float* b_fc1  = (const float*)d_in[12];
    const float* w_fc2  = (const float*)d_in[13];
    const float* b_fc2  = (const float*)d_in[14];
    float* out = (float*)d_out;

    __half *hwin, *qkv, *attn, *h2, *ff, *bq16, *wqkv, *wprj, *wf1, *wf2;
    float *x1;
    cudaGetSymbolAddress((void**)&hwin, g_hwin);
    cudaGetSymbolAddress((void**)&qkv,  g_qkv);
    cudaGetSymbolAddress((void**)&attn, g_attn);
    cudaGetSymbolAddress((void**)&x1,   g_x1);
    cudaGetSymbolAddress((void**)&h2,   g_h2);
    cudaGetSymbolAddress((void**)&ff,   g_ff);
    cudaGetSymbolAddress((void**)&bq16, g_bq16);
    cudaGetSymbolAddress((void**)&wqkv, g_wqkv);
    cudaGetSymbolAddress((void**)&wprj, g_wprj);
    cudaGetSymbolAddress((void**)&wf1,  g_wfc1);
    cudaGetSymbolAddress((void**)&wf2,  g_wfc2);

    cudaFuncSetAttribute(attn_kernel, cudaFuncAttributeMaxDynamicSharedMemorySize, ATTN_SMEM);
    cudaFuncSetAttribute(tgemm<1>, cudaFuncAttributeMaxDynamicSharedMemorySize, GSM_BYTES);
    cudaFuncSetAttribute(tgemm<2>, cudaFuncAttributeMaxDynamicSharedMemorySize, GSM_BYTES);
    cudaFuncSetAttribute(tgemm<3>, cudaFuncAttributeMaxDynamicSharedMemorySize, GSM_BYTES);

    // [0] LN1
    ln_kernel<<<M_TOK, 256>>>(x, g1, beta1, hwin);

    // [1-4] weight prep
    wprep<<<dim3(QKVN/32, EMBED/32), 256>>>(w_qkv,  wqkv, EMBED, QKVN);
    wprep<<<dim3(EMBED/32, EMBED/32), 256>>>(w_proj, wprj, EMBED, EMBED);
    wprep<<<dim3(FFDIM/32, EMBED/32), 256>>>(w_fc1,  wf1,  EMBED, FFDIM);
    wprep<<<dim3(EMBED/32, FFDIM/32), 256>>>(w_fc2,  wf2,  FFDIM, EMBED);

    // [5] QKV projection -> fp16
    tgemm<3><<<dim3(QKVN/128, M_TOK/256), 256, GSM_BYTES>>>(
        hwin, wqkv, b_qkv, nullptr, qkv, M_TOK, QKVN, EMBED, nullptr);

    // [6] bias -> fp16
    bprep<<<(QKVN + 255)/256, 256>>>(b_qkv, bq16, QKVN);

    // [7] window attention (tensor-core FA)
    attn_kernel<<<NWIN * NHEAD, 256, ATTN_SMEM>>>(qkv, bq16, relh, relw, attn);

    // [8] proj + residual: x1 = x + attn @ w_proj + b_proj
    tgemm<2><<<dim3(EMBED/128, M_TOK/256), 256, GSM_BYTES>>>(
        attn, wprj, b_proj, x1, nullptr, M_TOK, EMBED, EMBED, x);

    // [9] LN2
    ln_kernel<<<M_TOK, 256>>>(x1, g2, beta2, h2);

    // [10] fc1 + GELU -> fp16
    tgemm<1><<<dim3(FFDIM/128, M_TOK/256), 256, GSM_BYTES>>>(
        h2, wf1, b_fc1, nullptr, ff, M_TOK, FFDIM, EMBED, nullptr);

    // [11] fc2 + residual -> out
    tgemm<2><<<dim3(EMBED/128, M_TOK/256), 256, GSM_BYTES>>>(
        ff, wf2, b_fc2, out, nullptr, M_TOK, EMBED, FFDIM, x1);
}

// round 16
// speedup vs baseline: 1.0762x; 1.0762x over previous
#include <cuda_runtime.h>
#include <cuda_fp16.h>
#include <math.h>
#include <stdint.h>

// ---------------------------------------------------------------------------
// Problem constants
// ---------------------------------------------------------------------------
#define EMBED  768
#define NWIN   200
#define NTOK   196
#define NHEAD  12
#define HD     64
#define M_TOK  32768
#define FFDIM  3072
#define QKVN   2304

// ---------------------------------------------------------------------------
// Scratch (device globals; no allocation allowed)
// ---------------------------------------------------------------------------
__device__ __half g_hwin[(size_t)M_TOK*EMBED];
__device__ __half g_qkv [(size_t)M_TOK*QKVN];
__device__ __half g_attn[(size_t)M_TOK*EMBED];
__device__ float  g_x1  [(size_t)M_TOK*EMBED];
__device__ __half g_h2  [(size_t)M_TOK*EMBED];
__device__ __half g_ff  [(size_t)M_TOK*FFDIM];
__device__ __half g_bq16[QKVN];
// transposed fp16 weights: [N][K]
__device__ __half g_wqkv[(size_t)QKVN*EMBED];
__device__ __half g_wprj[(size_t)EMBED*EMBED];
__device__ __half g_wfc1[(size_t)FFDIM*EMBED];
__device__ __half g_wfc2[(size_t)EMBED*FFDIM];

// ---------------------------------------------------------------------------
// Helpers
// ---------------------------------------------------------------------------
__device__ __forceinline__ float gelu_f(float v) {
    return 0.5f * v * (1.0f + erff(v * 0.7071067811865476f));
}
__device__ __forceinline__ uint32_t s2u(const void* p) {
    uint32_t a;
    asm("{ .reg .u64 t; cvta.to.shared.u64 t, %1; cvt.u32.u64 %0, t; }" : "=r"(a) : "l"(p));
    return a;
}
__device__ __forceinline__ void ldsm_x4(uint32_t& r0, uint32_t& r1, uint32_t& r2,
                                        uint32_t& r3, uint32_t addr) {
    asm volatile("ldmatrix.sync.aligned.m8n8.x4.shared.b16 {%0,%1,%2,%3}, [%4];"
                 : "=r"(r0), "=r"(r1), "=r"(r2), "=r"(r3) : "r"(addr));
}
__device__ __forceinline__ void ldsm_x4t(uint32_t& r0, uint32_t& r1, uint32_t& r2,
                                         uint32_t& r3, uint32_t addr) {
    asm volatile("ldmatrix.sync.aligned.m8n8.x4.trans.shared.b16 {%0,%1,%2,%3}, [%4];"
                 : "=r"(r0), "=r"(r1), "=r"(r2), "=r"(r3) : "r"(addr));
}
__device__ __forceinline__ void mma16816(float* c, const uint32_t* a,
                                         uint32_t b0, uint32_t b1) {
    asm volatile(
        "mma.sync.aligned.m16n8k16.row.col.f32.f16.f16.f32 "
        "{%0,%1,%2,%3}, {%4,%5,%6,%7}, {%8,%9}, {%0,%1,%2,%3};"
        : "+f"(c[0]), "+f"(c[1]), "+f"(c[2]), "+f"(c[3])
        : "r"(a[0]), "r"(a[1]), "r"(a[2]), "r"(a[3]), "r"(b0), "r"(b1));
}
__device__ __forceinline__ void cp16(uint32_t saddr, const void* g) {
    asm volatile("cp.async.cg.shared.global [%0], [%1], 16;" :: "r"(saddr), "l"(g));
}
__device__ __forceinline__ void cp_commit() {
    asm volatile("cp.async.commit_group;");
}
__device__ __forceinline__ uint32_t packh2(float a, float b) {
    __half2 h = __floats2half2_rn(a, b);
    return *reinterpret_cast<uint32_t*>(&h);
}

// ---------------------------------------------------------------------------
// Weight prep: transpose [K,N] fp32 -> [N,K] fp16
// ---------------------------------------------------------------------------
__global__ __launch_bounds__(256) void wprep(
    const float* __restrict__ W, __half* __restrict__ T, int K, int N)
{
    __shared__ float t[32][33];
    const int n0 = blockIdx.x * 32, k0 = blockIdx.y * 32;
    const int tx = threadIdx.x & 31, ty = threadIdx.x >> 5;
    #pragma unroll
    for (int i = 0; i < 32; i += 8)
        t[ty + i][tx] = W[(size_t)(k0 + ty + i) * N + n0 + tx];
    __syncthreads();
    #pragma unroll
    for (int i = 0; i < 32; i += 8)
        T[(size_t)(n0 + ty + i) * K + k0 + tx] = __float2half(t[tx][ty + i]);
}

__global__ void bprep(const float* __restrict__ b, __half* __restrict__ o, int n) {
    int i = blockIdx.x * 256 + threadIdx.x;
    if (i < n) o[i] = __float2half(b[i]);
}

// ---------------------------------------------------------------------------
// LayerNorm -> fp16
// ---------------------------------------------------------------------------
__global__ __launch_bounds__(256) void ln_kernel(
    const float* __restrict__ xin, const float* __restrict__ g,
    const float* __restrict__ b, __half* __restrict__ oh)
{
    __shared__ float red[16];
    const int row = blockIdx.x, tid = threadIdx.x;
    const float* xr = xin + (size_t)row * EMBED;
    const size_t ro = (size_t)row * EMBED;
    float v0 = xr[tid], v1 = xr[tid+256], v2 = xr[tid+512];
    float s = v0+v1+v2, s2 = v0*v0+v1*v1+v2*v2;
    #pragma unroll
    for (int o = 16; o; o >>= 1) {
        s  += __shfl_xor_sync(0xffffffffu, s,  o);
        s2 += __shfl_xor_sync(0xffffffffu, s2, o);
    }
    if ((tid & 31) == 0) { red[tid>>5] = s; red[8+(tid>>5)] = s2; }
    __syncthreads();
    float S=0.f, S2=0.f;
    #pragma unroll
    for (int i = 0; i < 8; i++) { S += red[i]; S2 += red[8+i]; }
    const float mean = S * (1.f/768.f);
    const float rstd = rsqrtf(S2*(1.f/768.f) - mean*mean + 1e-6f);
    oh[ro+tid]     = __float2half((v0-mean)*rstd*g[tid]     + b[tid]);
    oh[ro+tid+256] = __float2half((v1-mean)*rstd*g[tid+256] + b[tid+256]);
    oh[ro+tid+512] = __float2half((v2-mean)*rstd*g[tid+512] + b[tid+512]);
}

// ---------------------------------------------------------------------------
// HMMA GEMM (fp16): C[M,N] = A[M,K] @ B[N,K]^T (+bias).
// CTA 128x128, 8 warps 64x32, K-chunk 64, double-buffered cp.async smem.
// (R12 configuration — empirically fastest.)
// EPI: 0 bias->fp32 | 1 bias+gelu->fp16 | 2 bias+res->fp32 | 3 bias->fp16
// ---------------------------------------------------------------------------
#define LDA        72                      // halves per smem row (64 + 8 pad)
#define TILE_BYTES (128*LDA*2)             // 18432
#define BUF_BYTES  (2*TILE_BYTES)          // A + B = 36864
#define GSM_BYTES  (2*BUF_BYTES)           // 73728

template<int EPI>
__global__ __launch_bounds__(256, 2) void tgemm(
    const __half* __restrict__ A, const __half* __restrict__ B,
    const float* __restrict__ bias, float* __restrict__ Co,
    __half* __restrict__ Ch, int M, int N, int K, const float* __restrict__ res)
{
    extern __shared__ char smc[];
    const uint32_t smb = s2u(smc);
    const int tid = threadIdx.x;
    const int wid = tid >> 5, lane = tid & 31;
    const int bm = blockIdx.y * 128, bn = blockIdx.x * 128;
    const int wm = wid & 1, wn = wid >> 1;
    const int NC = K >> 6;                   // K-chunks of 64

    float acc[4][4][4];
    #pragma unroll
    for (int i = 0; i < 4; i++)
        #pragma unroll
        for (int j = 0; j < 4; j++)
            #pragma unroll
            for (int k = 0; k < 4; k++) acc[i][j][k] = 0.f;

    const uint32_t offA = (uint32_t)((wm*64 + (lane & 7) + 8*((lane >> 3) & 1)) * LDA
                                     + 8*(lane >> 4)) * 2;
    const uint32_t offB = (uint32_t)((wn*32 + (lane & 7) + 8*(lane >> 4)) * LDA
                                     + 8*((lane >> 3) & 1)) * 2;

    auto load_chunk = [&](int c, int b) {
        const int k0 = c << 6;
        const uint32_t bb = smb + b * BUF_BYTES;
        #pragma unroll
        for (int a = 0; a < 2; a++) {
            const __half* G = a ? B : A;
            const int gb = a ? bn : bm;
            const uint32_t ab = bb + a * TILE_BYTES;
            #pragma unroll
            for (int s = 0; s < 4; s++) {
                const int u = tid + s * 256;        // [0,1024)
                const int row = u >> 3, seg = u & 7;
                cp16(ab + (uint32_t)(row * LDA + seg * 8) * 2,
                     G + (size_t)(gb + row) * K + k0 + seg * 8);
            }
        }
        cp_commit();
    };

    load_chunk(0, 0);

    for (int c = 0; c < NC; c++) {
        const int b = c & 1;
        if (c + 1 < NC) {
            load_chunk(c + 1, b ^ 1);
            asm volatile("cp.async.wait_group 1;");
        } else {
            asm volatile("cp.async.wait_group 0;");
        }
        __syncthreads();

        const uint32_t bb = smb + b * BUF_BYTES;
        const uint32_t pA = bb + offA;
        const uint32_t pB = bb + TILE_BYTES + offB;

        #pragma unroll
        for (int ks = 0; ks < 4; ks++) {
            const uint32_t kso = ks * 32;            // 16 halves = 32 bytes
            uint32_t ah[4][4], bh[4][2];
            #pragma unroll
            for (int mt = 0; mt < 4; mt++)
                ldsm_x4(ah[mt][0], ah[mt][1], ah[mt][2], ah[mt][3],
                        pA + kso + mt * (16*LDA*2));
            #pragma unroll
            for (int L = 0; L < 2; L++)
                ldsm_x4(bh[2*L][0], bh[2*L][1], bh[2*L+1][0], bh[2*L+1][1],
                        pB + kso + L * (16*LDA*2));
            #pragma unroll
            for (int mt = 0; mt < 4; mt++)
                #pragma unroll
                for (int nt = 0; nt < 4; nt++)
                    mma16816(acc[mt][nt], ah[mt], bh[nt][0], bh[nt][1]);
        }
        __syncthreads();
    }

    const int rbase = bm + wm*64;
    const int nbase = bn + wn*32;
    #pragma unroll
    for (int mt = 0; mt < 4; mt++) {
        #pragma unroll
        for (int half = 0; half < 2; half++) {
            const int m = rbase + mt*16 + (lane >> 2) + half*8;
            #pragma unroll
            for (int nt = 0; nt < 4; nt++) {
                const int n = nbase + nt*8 + (lane & 3)*2;
                float v0 = acc[mt][nt][half*2 + 0] + bias[n];
                float v1 = acc[mt][nt][half*2 + 1] + bias[n + 1];
                if (EPI == 0) {
                    *(float2*)(Co + (size_t)m * N + n) = make_float2(v0, v1);
                } else if (EPI == 1) {
                    __half2 H;
                    H.x = __float2half(gelu_f(v0));
                    H.y = __float2half(gelu_f(v1));
                    *(__half2*)(Ch + (size_t)m * N + n) = H;
                } else if (EPI == 2) {
                    const float2 r2 = *(const float2*)(res + (size_t)m * N + n);
                    *(float2*)(Co + (size_t)m * N + n) = make_float2(v0 + r2.x, v1 + r2.y);
                } else {
                    __half2 H;
                    H.x = __float2half(v0); H.y = __float2half(v1);
                    *(__half2*)(Ch + (size_t)m * N + n) = H;
                }
            }
        }
    }
}

// ---------------------------------------------------------------------------
// FA2-style window attention on mma.sync. One (window, head) per CTA.
// 416 threads = 13 warps; each warp owns exactly ONE m16 q-tile (no imbalance).
// ---------------------------------------------------------------------------
#define ATHREADS 416
#define LDH   72           // halves per smem row
#define LDR   72           // rel-pos table row stride (bank-spread)
#define NPAD  208          // tokens padded to 13 x m16
#define OFF_Q 0
#define OFF_K (NPAD*LDH*2)
#define OFF_V (2*NPAD*LDH*2)
#define OFF_RH (3*NPAD*LDH*2)          // 27*LDR halves
#define OFF_RW (OFF_RH + 27*LDR*2)
#define OFF_BH (OFF_RW + 27*LDR*2)     // 196*14 halves
#define OFF_BW (OFF_BH + 196*14*2)
#define ATTN_SMEM (OFF_BW + 196*14*2)  // 108608 B

__global__ __launch_bounds__(ATHREADS, 1) void attn_kernel(
    const __half* __restrict__ qkv, const __half* __restrict__ bq16,
    const float* __restrict__ relh, const float* __restrict__ relw,
    __half* __restrict__ ao)
{
    extern __shared__ char smc[];
    const uint32_t smb = s2u(smc);
    __half* Qh = (__half*)(smc + OFF_Q);
    __half* Kh = (__half*)(smc + OFF_K);
    __half* Vh = (__half*)(smc + OFF_V);
    __half* Rh = (__half*)(smc + OFF_RH);
    __half* Rw = (__half*)(smc + OFF_RW);
    __half* BH = (__half*)(smc + OFF_BH);
    __half* BW = (__half*)(smc + OFF_BW);

    const int tid = threadIdx.x;
    const int w = blockIdx.x / NHEAD, h = blockIdx.x % NHEAD;
    const int bI = w / 25, wr = w % 25;
    const int wy = wr / 5, wx = wr % 5;
    const int wid = tid >> 5, lane = tid & 31;

    // ---- load Q,K,V (fp16) with window gather; pad rows with zeros ----
    for (int idx = tid; idx < NTOK * 8; idx += ATHREADS) {
        const int t = idx >> 3, seg = idx & 7;
        const int y = wy * 14 + t / 14, xx = wx * 14 + t % 14;
        const __half* rp = (y < 64 && xx < 64)
            ? qkv + (size_t)((bI * 64 + y) * 64 + xx) * QKVN + h * HD + seg * 8
            : bq16 + h * HD + seg * 8;
        *(uint4*)&Qh[t * LDH + seg * 8] = *(const uint4*)(rp);
        *(uint4*)&Kh[t * LDH + seg * 8] = *(const uint4*)(rp + 768);
        *(uint4*)&Vh[t * LDH + seg * 8] = *(const uint4*)(rp + 1536);
    }
    for (int idx = tid; idx < (NPAD - NTOK) * 8; idx += ATHREADS) {
        const int t = NTOK + (idx >> 3), seg = idx & 7;
        const uint4 z = make_uint4(0, 0, 0, 0);
        *(uint4*)&Qh[t * LDH + seg * 8] = z;
        *(uint4*)&Kh[t * LDH + seg * 8] = z;
        *(uint4*)&Vh[t * LDH + seg * 8] = z;
    }
    for (int idx = tid; idx < 27 * 64; idx += ATHREADS) {
        const int rr = idx >> 6, cc = idx & 63;
        Rh[rr * LDR + cc] = __float2half(relh[idx]);
        Rw[rr * LDR + cc] = __float2half(relw[idx]);
    }
    __syncthreads();

    // ---- rel-pos bias tables: lane L owns (r = L>>1, d-half = L&1) ----
    for (int i = wid; i < NTOK; i += 13) {
        const int p = i / 14, qc = i % 14;
        if (lane < 28) {
            const int r = lane >> 1, hf = lane & 1;
            const __half* qrow  = &Qh[i * LDH + hf * 32];
            const __half* rhrow = &Rh[(p  + 13 - r) * LDR + hf * 32];
            const __half* rwrow = &Rw[(qc + 13 - r) * LDR + hf * 32];
            float ah = 0.f, aw = 0.f;
            #pragma unroll
            for (int k = 0; k < 16; k++) {
                const float2 q2 = __half22float2(*(const __half2*)(qrow + 2*k));
                const float2 h2 = __half22float2(*(const __half2*)(rhrow + 2*k));
                const float2 w2 = __half22float2(*(const __half2*)(rwrow + 2*k));
                ah += q2.x * h2.x + q2.y * h2.y;
                aw += q2.x * w2.x + q2.y * w2.y;
            }
            ah += __shfl_xor_sync(0x0fffffffu, ah, 1);
            aw += __shfl_xor_sync(0x0fffffffu, aw, 1);
            if (hf == 0) {
                BH[i*14 + r] = __float2half(ah);
                BW[i*14 + r] = __float2half(aw);
            }
        }
    }
    __syncthreads();

    const float SCALE = 0.125f;
    const uint32_t qb = smb + OFF_Q, kb = smb + OFF_K, vb = smb + OFF_V;

    // ---- one m16 q-tile per warp: online-softmax over 13 key chunks ----
    {
        const int tile = wid;    // 13 warps, 13 tiles
        uint32_t aq[4][4];
        #pragma unroll
        for (int kk = 0; kk < 4; kk++)
            ldsm_x4(aq[kk][0], aq[kk][1], aq[kk][2], aq[kk][3],
                    qb + (uint32_t)((tile*16 + (lane&7) + 8*((lane>>3)&1)) * LDH
                                    + kk*16 + 8*(lane>>4)) * 2);

        float o[8][4];
        #pragma unroll
        for (int i = 0; i < 8; i++)
            #pragma unroll
            for (int j = 0; j < 4; j++) o[i][j] = 0.f;
        float mrun0 = -1e30f, mrun1 = -1e30f, lrun0 = 0.f, lrun1 = 0.f;

        const int i0 = tile*16 + (lane >> 2);
        const int i0c = (i0 < NTOK ? i0 : 0), i1c = (i0 + 8 < NTOK ? i0 + 8 : 0);

        for (int kc = 0; kc < 13; kc++) {
            float S0[4], S1[4];
            #pragma unroll
            for (int j = 0; j < 4; j++) { S0[j] = 0.f; S1[j] = 0.f; }
            #pragma unroll
            for (int kk = 0; kk < 4; kk++) {
                uint32_t r0, r1, r2, r3;
                ldsm_x4(r0, r1, r2, r3,
                        kb + (uint32_t)((kc*16 + (lane&7) + 8*(lane>>4)) * LDH
                                        + kk*16 + 8*((lane>>3)&1)) * 2);
                mma16816(S0, aq[kk], r0, r1);
                mma16816(S1, aq[kk], r2, r3);
            }
            const int j0 = kc*16 + 2*(lane & 3);
            float s[2][4];
            #pragma unroll
            for (int e = 0; e < 4; e++) {
                const int j = j0 + (e & 1) + (e >> 1) * 8;
                bool ok = (j < NTOK);
                int jp = 0, jq = 0;
                if (ok) { jp = j / 14; jq = j - jp * 14; }
                const float b0 = __half2float(BH[i0c*14+jp]) + __half2float(BW[i0c*14+jq]);
                const float b1 = __half2float(BH[i1c*14+jp]) + __half2float(BW[i1c*14+jq]);
                const float r0v = (e >> 1) ? S1[e & 1] : S0[e & 1];
                const float r1v = (e >> 1) ? S1[2 + (e & 1)] : S0[2 + (e & 1)];
                s[0][e] = ok ? r0v * SCALE + b0 : -1e30f;
                s[1][e] = ok ? r1v * SCALE + b1 : -1e30f;
            }
            float mx0 = fmaxf(fmaxf(s[0][0], s[0][1]), fmaxf(s[0][2], s[0][3]));
            float mx1 = fmaxf(fmaxf(s[1][0], s[1][1]), fmaxf(s[1][2], s[1][3]));
            mx0 = fmaxf(mx0, __shfl_xor_sync(0xffffffffu, mx0, 1));
            mx0 = fmaxf(mx0, __shfl_xor_sync(0xffffffffu, mx0, 2));
            mx1 = fmaxf(mx1, __shfl_xor_sync(0xffffffffu, mx1, 1));
            mx1 = fmaxf(mx1, __shfl_xor_sync(0xffffffffu, mx1, 2));
            const float mn0 = fmaxf(mrun0, mx0), mn1 = fmaxf(mrun1, mx1);
            float sc0 = 1.f, sc1 = 1.f;
            const bool nochange = (mn0 == mrun0) && (mn1 == mrun1);
            if (!__all_sync(0xffffffffu, nochange)) {
                sc0 = __expf(mrun0 - mn0);
                sc1 = __expf(mrun1 - mn1);
                #pragma unroll
                for (int dt = 0; dt < 8; dt++) {
                    o[dt][0] *= sc0; o[dt][1] *= sc0;
                    o[dt][2] *= sc1; o[dt][3] *= sc1;
                }
            }
            mrun0 = mn0; mrun1 = mn1;
            float p[2][4], rs0 = 0.f, rs1 = 0.f;
            #pragma unroll
            for (int e = 0; e < 4; e++) {
                p[0][e] = __expf(s[0][e] - mn0);
                p[1][e] = __expf(s[1][e] - mn1);
                rs0 += p[0][e]; rs1 += p[1][e];
            }
            rs0 += __shfl_xor_sync(0xffffffffu, rs0, 1);
            rs0 += __shfl_xor_sync(0xffffffffu, rs0, 2);
            rs1 += __shfl_xor_sync(0xffffffffu, rs1, 1);
            rs1 += __shfl_xor_sync(0xffffffffu, rs1, 2);
            lrun0 = lrun0 * sc0 + rs0;
            lrun1 = lrun1 * sc1 + rs1;
            uint32_t ap[4];
            ap[0] = packh2(p[0][0], p[0][1]);
            ap[1] = packh2(p[1][0], p[1][1]);
            ap[2] = packh2(p[0][2], p[0][3]);
            ap[3] = packh2(p[1][2], p[1][3]);
            #pragma unroll
            for (int nn = 0; nn < 4; nn++) {
                uint32_t r0, r1, r2, r3;
                ldsm_x4t(r0, r1, r2, r3,
                         vb + (uint32_t)((kc*16 + (lane & 15)) * LDH
                                         + nn*16 + 8*(lane>>4)) * 2);
                mma16816(o[2*nn],     ap, r0, r1);
                mma16816(o[2*nn + 1], ap, r2, r3);
            }
        }

        // ---- write out (scatter to compact layout) ----
        const float inv0 = 1.f / lrun0, inv1 = 1.f / lrun1;
        #pragma unroll
        for (int half = 0; half < 2; half++) {
            const int i = tile*16 + (lane >> 2) + half*8;
            if (i < NTOK) {
                const int y = wy*14 + i/14, xx = wx*14 + i%14;
                if (y < 64 && xx < 64) {
                    __half* orow = ao + (size_t)((bI*64 + y)*64 + xx) * EMBED + h * HD;
                    const float inv = half ? inv1 : inv0;
                    #pragma unroll
                    for (int dt = 0; dt < 8; dt++) {
                        __half2 H;
                        H.x = __float2half(o[dt][half*2 + 0] * inv);
                        H.y = __float2half(o[dt][half*2 + 1] * inv);
                        *(__half2*)(orow + dt*8 + 2*(lane & 3)) = H;
                    }
                }
            }
        }
    }
}

// ---------------------------------------------------------------------------
// kernel_launch
// ---------------------------------------------------------------------------
extern "C" void kernel_launch(void* const* d_in, const int* in_sizes, int n_in,
                              void* d_out, int out_size)
{
    const float* x      = (const float*)d_in[0];
    const float* g1     = (const float*)d_in[1];
    const float* beta1  = (const float*)d_in[2];
    const float* w_qkv  = (const float*)d_in[3];
    const float* b_qkv  = (const float*)d_in[4];
    const float* w_proj = (const float*)d_in[5];
    const float* b_proj = (const float*)d_in[6];
    const float* relh   = (const float*)d_in[7];
    const float* relw   = (const float*)d_in[8];
    const float* g2     = (const float*)d_in[9];
    const float* beta2  = (const float*)d_in[10];
    const float* w_fc1  = (const float*)d_in[11];
    const float* b_fc1  = (const float*)d_in[12];
    const float* w_fc2  = (const float*)d_in[13];
    const float* b_fc2  = (const float*)d_in[14];
    float* out = (float*)d_out;

    __half *hwin, *qkv, *attn, *h2, *ff, *bq16, *wqkv, *wprj, *wf1, *wf2;
    float *x1;
    cudaGetSymbolAddress((void**)&hwin, g_hwin);
    cudaGetSymbolAddress((void**)&qkv,  g_qkv);
    cudaGetSymbolAddress((void**)&attn, g_attn);
    cudaGetSymbolAddress((void**)&x1,   g_x1);
    cudaGetSymbolAddress((void**)&h2,   g_h2);
    cudaGetSymbolAddress((void**)&ff,   g_ff);
    cudaGetSymbolAddress((void**)&bq16, g_bq16);
    cudaGetSymbolAddress((void**)&wqkv, g_wqkv);
    cudaGetSymbolAddress((void**)&wprj, g_wprj);
    cudaGetSymbolAddress((void**)&wf1,  g_wfc1);
    cudaGetSymbolAddress((void**)&wf2,  g_wfc2);

    cudaFuncSetAttribute(attn_kernel, cudaFuncAttributeMaxDynamicSharedMemorySize, ATTN_SMEM);
    cudaFuncSetAttribute(tgemm<1>, cudaFuncAttributeMaxDynamicSharedMemorySize, GSM_BYTES);
    cudaFuncSetAttribute(tgemm<2>, cudaFuncAttributeMaxDynamicSharedMemorySize, GSM_BYTES);
    cudaFuncSetAttribute(tgemm<3>, cudaFuncAttributeMaxDynamicSharedMemorySize, GSM_BYTES);

    // [0] LN1
    ln_kernel<<<M_TOK, 256>>>(x, g1, beta1, hwin);

    // [1-4] weight prep
    wprep<<<dim3(QKVN/32, EMBED/32), 256>>>(w_qkv,  wqkv, EMBED, QKVN);
    wprep<<<dim3(EMBED/32, EMBED/32), 256>>>(w_proj, wprj, EMBED, EMBED);
    wprep<<<dim3(FFDIM/32, EMBED/32), 256>>>(w_fc1,  wf1,  EMBED, FFDIM);
    wprep<<<dim3(EMBED/32, FFDIM/32), 256>>>(w_fc2,  wf2,  FFDIM, EMBED);

    // [5] QKV projection -> fp16
    tgemm<3><<<dim3(QKVN/128, M_TOK/128), 256, GSM_BYTES>>>(
        hwin, wqkv, b_qkv, nullptr, qkv, M_TOK, QKVN, EMBED, nullptr);

    // [6] bias -> fp16
    bprep<<<(QKVN + 255)/256, 256>>>(b_qkv, bq16, QKVN);

    // [7] window attention (tensor-core FA, 13 warps)
    attn_kernel<<<NWIN * NHEAD, ATHREADS, ATTN_SMEM>>>(qkv, bq16, relh, relw, attn);

    // [8] proj + residual: x1 = x + attn @ w_proj + b_proj
    tgemm<2><<<dim3(EMBED/128, M_TOK/128), 256, GSM_BYTES>>>(
        attn, wprj, b_proj, x1, nullptr, M_TOK, EMBED, EMBED, x);

    // [9] LN2
    ln_kernel<<<M_TOK, 256>>>(x1, g2, beta2, h2);

    // [10] fc1 + GELU -> fp16
    tgemm<1><<<dim3(FFDIM/128, M_TOK/128), 256, GSM_BYTES>>>(
        h2, wf1, b_fc1, nullptr, ff, M_TOK, FFDIM, EMBED, nullptr);

    // [11] fc2 + residual -> out
    tgemm<2><<<dim3(EMBED/128, M_TOK/128), 256, GSM_BYTES>>>(
        ff, wf2, b_fc2, out, nullptr, M_TOK, EMBED, FFDIM, x1);
}